// round 8
// baseline (speedup 1.0000x reference)
#include <cuda_runtime.h>
#include <math.h>

#define DD 128
#define WIN 15
#define WW (2*WIN+1)          // 31
#define MAXB 4
#define MAXS 4096
#define RPB 8                 // band rows per block
#define TROWS (RPB + 2*WIN)   // 38 smem rows

__device__ float g_band[(size_t)MAXB*MAXS*WW];
__device__ float g_dinv[MAXB*MAXS];

__device__ __forceinline__ void stg256_cs(float* p, const float4& a, const float4& b) {
    asm volatile("st.global.cs.v8.f32 [%0], {%1,%2,%3,%4,%5,%6,%7,%8};"
                 :: "l"(p),
                    "f"(a.x), "f"(a.y), "f"(a.z), "f"(a.w),
                    "f"(b.x), "f"(b.y), "f"(b.z), "f"(b.w)
                 : "memory");
}

// fast acos: Abramowitz-Stegun 4.4.45, |err| <= 6.7e-5 rad
__device__ __forceinline__ float angular_weight(float c) {
    float ax = fabsf(c);
    float s = sqrtf(fmaxf(1.f - ax, 0.f));
    float p = s * (1.5707288f + ax * (-0.2121144f + ax * (0.0742610f - ax * 0.0187293f)));
    float ac = (c >= 0.f) ? p : (3.14159265358979f - p);
    return 1.f - ac * 0.31830988618379067f;   // 1 - acos/pi
}

// ---------------- Kernel 1: fused norms + speakers + band + dinv ----------------
__global__ __launch_bounds__(256)
void bandprep_kernel(const float* __restrict__ x,
                     const float* __restrict__ qmask,
                     const int* __restrict__ dia_len,
                     int B, int S, int NSPK) {
    __shared__ float sx[TROWS * DD];   // normalized rows
    __shared__ int   sspk[TROWS];

    int b  = blockIdx.y;
    int i0 = blockIdx.x * RPB;
    int base = b * S;
    int len = dia_len[b];
    int gr0 = i0 - WIN;

    float4* sx4 = (float4*)sx;
    const float4* x4g = (const float4*)(x + (size_t)base * DD);

    // ---- Phase A: load rows [gr0, gr0+38), normalize, store to smem ----
    // ALL lanes execute the shfl reduce (warp-converged); stores predicated.
    {
        int sub = threadIdx.x & 7;     // 8 threads per row, 32 rows per pass
#pragma unroll
        for (int pass = 0; pass < 2; pass++) {
            int r = pass * 32 + (threadIdx.x >> 3);
            int gr = gr0 + r;
            bool inb = (r < TROWS) && (gr >= 0) && (gr < S);
            float4 v[4];
            float ss = 0.f;
            if (inb) {
#pragma unroll
                for (int k = 0; k < 4; k++) {
                    v[k] = x4g[(size_t)gr * (DD/4) + sub * 4 + k];
                    ss += v[k].x * v[k].x + v[k].y * v[k].y
                        + v[k].z * v[k].z + v[k].w * v[k].w;
                }
            } else {
#pragma unroll
                for (int k = 0; k < 4; k++) v[k] = make_float4(0.f, 0.f, 0.f, 0.f);
            }
#pragma unroll
            for (int off = 4; off; off >>= 1)
                ss += __shfl_xor_sync(0xffffffffu, ss, off);
            float inv = 1.f / fmaxf(sqrtf(ss), 1e-8f);
            if (r < TROWS) {
#pragma unroll
                for (int k = 0; k < 4; k++) {
                    v[k].x *= inv; v[k].y *= inv; v[k].z *= inv; v[k].w *= inv;
                    sx4[r * (DD/4) + sub * 4 + k] = v[k];
                }
            }
        }
        if (threadIdx.x < TROWS) {
            int gr = gr0 + threadIdx.x;
            int bi = -1;
            if (gr >= 0 && gr < S) {
                const float* q = qmask + ((size_t)gr * B + b) * NSPK;
                float best = q[0]; bi = 0;
                for (int k = 1; k < NSPK; k++) {
                    float v = q[k];
                    if (v > best) { best = v; bi = k; }  // JAX first-max
                }
            }
            sspk[threadIdx.x] = bi;
        }
    }
    __syncthreads();

    // ---- Phase B: warp w handles row i = i0 + w ----
    int w = threadIdx.x >> 5;
    int lane = threadIdx.x & 31;
    int i = i0 + w;
    if (i >= S) return;
    int li = WIN + w;
    bool valid_i = (i < len);          // warp-uniform
    int spk_i = sspk[li];

    float4 xi = sx4[li * (DD/4) + lane];

    int cnt = 0;
    {
        bool p = false;
        if (lane < WW) {
            int j = i - WIN + lane;
            p = valid_i && (j >= 0 && j < len && sspk[w + lane] == spk_i);
        }
        cnt = __popc(__ballot_sync(0xffffffffu, p));
    }

    float deg = 0.f;
    float* bp = g_band + (size_t)(base + i) * WW;
#pragma unroll
    for (int jj = 0; jj < WW; jj++) {
        int j = i - WIN + jj;          // warp-uniform
        float a = 0.f;
        if (valid_i && j >= 0 && j < len) {
            float4 xj = sx4[(w + jj) * (DD/4) + lane];
            float dot = xi.x * xj.x + xi.y * xj.y + xi.z * xj.z + xi.w * xj.w;
#pragma unroll
            for (int off = 16; off; off >>= 1)
                dot += __shfl_xor_sync(0xffffffffu, dot, off);
            float c = fminf(fmaxf(dot, -1.f), 1.f);
            float wgt = angular_weight(c);
            bool same = (sspk[w + jj] == spk_i);
            a = wgt * ((cnt > 1 && same) ? 2.f : 1.f);
            deg += a;
        }
        if (lane == jj) bp[jj] = a;
    }
    if (lane == 0)
        g_dinv[base + i] = (deg > 0.f) ? rsqrtf(deg) : 1.f;
}

// ---------------- Kernel 2: fused zero-fill + band patch (256-bit stores) ----------------
__global__ __launch_bounds__(256)
void fill_kernel(float* __restrict__ out, int B, int S) {
    int row = blockIdx.x;              // b*S + i
    int b = row / S, i = row % S;
    float di = g_dinv[row];
    const float* bp = g_band + (size_t)row * WW;
    float* orow = out + (size_t)row * S;
    int lo = i - WIN;

    int nch = S >> 3;                  // 8 floats per chunk
    for (int c = threadIdx.x; c < nch; c += blockDim.x) {
        int j0 = c << 3;
        float4 va = make_float4(0.f, 0.f, 0.f, 0.f);
        float4 vb = make_float4(0.f, 0.f, 0.f, 0.f);
        int d0 = j0 - lo;
        if (d0 > -8 && d0 < WW) {      // chunk overlaps the band
            float v[8];
#pragma unroll
            for (int e = 0; e < 8; e++) {
                int d = d0 + e, j = j0 + e;
                v[e] = (d >= 0 && d < WW && j < S)
                       ? bp[d] * di * g_dinv[b * S + j] : 0.f;
            }
            va = make_float4(v[0], v[1], v[2], v[3]);
            vb = make_float4(v[4], v[5], v[6], v[7]);
        }
        stg256_cs(orow + j0, va, vb);
    }
}

extern "C" void kernel_launch(void* const* d_in, const int* in_sizes, int n_in,
                              void* d_out, int out_size) {
    const float* x       = (const float*)d_in[0];
    const float* qmask   = (const float*)d_in[1];
    const int*   dia_len = (const int*)d_in[2];
    float* out = (float*)d_out;

    int B = in_sizes[2];
    int S = in_sizes[0] / (B * DD);
    int NSPK = in_sizes[1] / (B * S);
    int n = B * S;

    dim3 bgrid((S + RPB - 1) / RPB, B);
    bandprep_kernel<<<bgrid, 256>>>(x, qmask, dia_len, B, S, NSPK);

    fill_kernel<<<n, 256>>>(out, B, S);
}

// round 9
// speedup vs baseline: 1.1180x; 1.1180x over previous
#include <cuda_runtime.h>
#include <math.h>

#define DD 128
#define WIN 15
#define WW (2*WIN+1)          // 31
#define MAXB 4
#define MAXS 4096
#define RPB 8                 // band rows per block
#define TROWS (RPB + 2*WIN)   // 38 smem rows
#define RPAD 132              // padded row stride in floats (33 float4)
#define RP4  (RPAD/4)         // 33

__device__ float g_band[(size_t)MAXB*MAXS*WW];
__device__ float g_dinv[MAXB*MAXS];

__device__ __forceinline__ void stg256_cs(float* p, const float4& a, const float4& b) {
    asm volatile("st.global.cs.v8.f32 [%0], {%1,%2,%3,%4,%5,%6,%7,%8};"
                 :: "l"(p),
                    "f"(a.x), "f"(a.y), "f"(a.z), "f"(a.w),
                    "f"(b.x), "f"(b.y), "f"(b.z), "f"(b.w)
                 : "memory");
}

// fast acos: Abramowitz-Stegun 4.4.45, |err| <= 6.7e-5 rad
__device__ __forceinline__ float angular_weight(float c) {
    float ax = fabsf(c);
    float s = sqrtf(fmaxf(1.f - ax, 0.f));
    float p = s * (1.5707288f + ax * (-0.2121144f + ax * (0.0742610f - ax * 0.0187293f)));
    float ac = (c >= 0.f) ? p : (3.14159265358979f - p);
    return 1.f - ac * 0.31830988618379067f;   // 1 - acos/pi
}

// ---------------- Kernel 1: fused norms + speakers + band + dinv ----------------
__global__ __launch_bounds__(256)
void bandprep_kernel(const float* __restrict__ x,
                     const float* __restrict__ qmask,
                     const int* __restrict__ dia_len,
                     int B, int S, int NSPK) {
    __shared__ float sx[TROWS * RPAD]; // normalized rows, padded stride
    __shared__ int   sspk[TROWS];

    int b  = blockIdx.y;
    int i0 = blockIdx.x * RPB;
    int base = b * S;
    int len = dia_len[b];
    int gr0 = i0 - WIN;

    float4* sx4 = (float4*)sx;
    const float4* x4g = (const float4*)(x + (size_t)base * DD);

    // ---- Phase A: load rows [gr0, gr0+38), normalize, store to smem ----
    // ALL lanes run the shfl reduce (warp-converged); stores predicated.
    {
        int sub = threadIdx.x & 7;     // 8 threads per row, 32 rows per pass
#pragma unroll
        for (int pass = 0; pass < 2; pass++) {
            int r = pass * 32 + (threadIdx.x >> 3);
            int gr = gr0 + r;
            bool inb = (r < TROWS) && (gr >= 0) && (gr < S);
            float4 v[4];
            float ss = 0.f;
            if (inb) {
#pragma unroll
                for (int k = 0; k < 4; k++) {
                    v[k] = x4g[(size_t)gr * (DD/4) + sub * 4 + k];
                    ss += v[k].x * v[k].x + v[k].y * v[k].y
                        + v[k].z * v[k].z + v[k].w * v[k].w;
                }
            } else {
#pragma unroll
                for (int k = 0; k < 4; k++) v[k] = make_float4(0.f, 0.f, 0.f, 0.f);
            }
#pragma unroll
            for (int off = 4; off; off >>= 1)
                ss += __shfl_xor_sync(0xffffffffu, ss, off);
            float inv = 1.f / fmaxf(sqrtf(ss), 1e-8f);
            if (r < TROWS) {
#pragma unroll
                for (int k = 0; k < 4; k++) {
                    v[k].x *= inv; v[k].y *= inv; v[k].z *= inv; v[k].w *= inv;
                    sx4[r * RP4 + sub * 4 + k] = v[k];
                }
            }
        }
        if (threadIdx.x < TROWS) {
            int gr = gr0 + threadIdx.x;
            int bi = -1;
            if (gr >= 0 && gr < S) {
                const float* q = qmask + ((size_t)gr * B + b) * NSPK;
                float best = q[0]; bi = 0;
                for (int k = 1; k < NSPK; k++) {
                    float v = q[k];
                    if (v > best) { best = v; bi = k; }  // JAX first-max
                }
            }
            sspk[threadIdx.x] = bi;
        }
    }
    __syncthreads();

    // ---- Phase B: warp w owns row i = i0 + w; LANE jj owns neighbor j ----
    int w = threadIdx.x >> 5;
    int lane = threadIdx.x & 31;
    int i = i0 + w;
    if (i >= S) return;
    int li = WIN + w;                  // smem row of i
    bool valid_i = (i < len);          // warp-uniform
    int spk_i = sspk[li];

    int j = i - WIN + lane;            // this lane's neighbor (lane 31 idle)
    int lj = w + lane;                 // its smem row (clamp for safety)
    if (lj >= TROWS) lj = TROWS - 1;
    bool valid_j = (lane < WW) && valid_i && (j >= 0) && (j < len);
    bool same = valid_j && (sspk[lj] == spk_i);

    // same-speaker count via ballot
    int cnt = __popc(__ballot_sync(0xffffffffu, same));

    // full 128-length dot per lane: xi broadcast, xj strided (4-phase LDS)
    float dot = 0.f;
    const float4* xi4 = sx4 + li * RP4;
    const float4* xj4 = sx4 + lj * RP4;
#pragma unroll
    for (int k = 0; k < DD/4; k++) {
        float4 a4 = xi4[k];            // broadcast (same addr all lanes)
        float4 b4 = xj4[k];
        dot += a4.x * b4.x + a4.y * b4.y + a4.z * b4.z + a4.w * b4.w;
    }

    float a = 0.f;
    if (valid_j) {
        float c = fminf(fmaxf(dot, -1.f), 1.f);
        float wgt = angular_weight(c);
        a = wgt * ((cnt > 1 && same) ? 2.f : 1.f);
    }

    // degree = sum of a over lanes (lane31 contributes 0)
    float deg = a;
#pragma unroll
    for (int off = 16; off; off >>= 1)
        deg += __shfl_xor_sync(0xffffffffu, deg, off);

    if (lane < WW) g_band[(size_t)(base + i) * WW + lane] = a;
    if (lane == 0)
        g_dinv[base + i] = (deg > 0.f) ? rsqrtf(deg) : 1.f;
}

// ---------------- Kernel 2: fused zero-fill + band patch (256-bit stores) ----------------
__global__ __launch_bounds__(256)
void fill_kernel(float* __restrict__ out, int B, int S) {
    int row = blockIdx.x;              // b*S + i
    int b = row / S, i = row % S;
    float di = g_dinv[row];
    const float* bp = g_band + (size_t)row * WW;
    float* orow = out + (size_t)row * S;
    int lo = i - WIN;

    int nch = S >> 3;                  // 8 floats per chunk
    for (int c = threadIdx.x; c < nch; c += blockDim.x) {
        int j0 = c << 3;
        float4 va = make_float4(0.f, 0.f, 0.f, 0.f);
        float4 vb = make_float4(0.f, 0.f, 0.f, 0.f);
        int d0 = j0 - lo;
        if (d0 > -8 && d0 < WW) {      // chunk overlaps the band
            float v[8];
#pragma unroll
            for (int e = 0; e < 8; e++) {
                int d = d0 + e, j = j0 + e;
                v[e] = (d >= 0 && d < WW && j < S)
                       ? bp[d] * di * g_dinv[b * S + j] : 0.f;
            }
            va = make_float4(v[0], v[1], v[2], v[3]);
            vb = make_float4(v[4], v[5], v[6], v[7]);
        }
        stg256_cs(orow + j0, va, vb);
    }
}

extern "C" void kernel_launch(void* const* d_in, const int* in_sizes, int n_in,
                              void* d_out, int out_size) {
    const float* x       = (const float*)d_in[0];
    const float* qmask   = (const float*)d_in[1];
    const int*   dia_len = (const int*)d_in[2];
    float* out = (float*)d_out;

    int B = in_sizes[2];
    int S = in_sizes[0] / (B * DD);
    int NSPK = in_sizes[1] / (B * S);
    int n = B * S;

    dim3 bgrid((S + RPB - 1) / RPB, B);
    bandprep_kernel<<<bgrid, 256>>>(x, qmask, dia_len, B, S, NSPK);

    fill_kernel<<<n, 256>>>(out, B, S);
}

// round 10
// speedup vs baseline: 1.1793x; 1.0548x over previous
#include <cuda_runtime.h>
#include <math.h>

#define DD 128
#define WIN 15
#define WW (2*WIN+1)          // 31
#define MAXB 4
#define MAXS 4096
#define RPB 8                 // band rows per block
#define TROWS (RPB + 2*WIN)   // 38 smem rows
#define RPAD 132              // padded row stride in floats
#define RP4  (RPAD/4)         // 33

__device__ float g_band[(size_t)MAXB*MAXS*WW];
__device__ float g_dinv[MAXB*MAXS];

__device__ __forceinline__ void stg256_cs(float* p, const float4& a, const float4& b) {
    asm volatile("st.global.cs.v8.f32 [%0], {%1,%2,%3,%4,%5,%6,%7,%8};"
                 :: "l"(p),
                    "f"(a.x), "f"(a.y), "f"(a.z), "f"(a.w),
                    "f"(b.x), "f"(b.y), "f"(b.z), "f"(b.w)
                 : "memory");
}

// fast acos: Abramowitz-Stegun 4.4.45, |err| <= 6.7e-5 rad
__device__ __forceinline__ float angular_weight(float c) {
    float ax = fabsf(c);
    float s = sqrtf(fmaxf(1.f - ax, 0.f));
    float p = s * (1.5707288f + ax * (-0.2121144f + ax * (0.0742610f - ax * 0.0187293f)));
    float ac = (c >= 0.f) ? p : (3.14159265358979f - p);
    return 1.f - ac * 0.31830988618379067f;   // 1 - acos/pi
}

// ---------------- bandprep: norms + speakers + band + dinv (side stream) ----------------
__global__ __launch_bounds__(256)
void bandprep_kernel(const float* __restrict__ x,
                     const float* __restrict__ qmask,
                     const int* __restrict__ dia_len,
                     int B, int S, int NSPK) {
    __shared__ float sx[TROWS * RPAD];
    __shared__ int   sspk[TROWS];

    int b  = blockIdx.y;
    int i0 = blockIdx.x * RPB;
    int base = b * S;
    int len = dia_len[b];
    int gr0 = i0 - WIN;

    float4* sx4 = (float4*)sx;
    const float4* x4g = (const float4*)(x + (size_t)base * DD);

    // Phase A: load + normalize rows into smem (shfl kept warp-converged)
    {
        int sub = threadIdx.x & 7;
#pragma unroll
        for (int pass = 0; pass < 2; pass++) {
            int r = pass * 32 + (threadIdx.x >> 3);
            int gr = gr0 + r;
            bool inb = (r < TROWS) && (gr >= 0) && (gr < S);
            float4 v[4];
            float ss = 0.f;
            if (inb) {
#pragma unroll
                for (int k = 0; k < 4; k++) {
                    v[k] = x4g[(size_t)gr * (DD/4) + sub * 4 + k];
                    ss += v[k].x * v[k].x + v[k].y * v[k].y
                        + v[k].z * v[k].z + v[k].w * v[k].w;
                }
            } else {
#pragma unroll
                for (int k = 0; k < 4; k++) v[k] = make_float4(0.f, 0.f, 0.f, 0.f);
            }
#pragma unroll
            for (int off = 4; off; off >>= 1)
                ss += __shfl_xor_sync(0xffffffffu, ss, off);
            float inv = 1.f / fmaxf(sqrtf(ss), 1e-8f);
            if (r < TROWS) {
#pragma unroll
                for (int k = 0; k < 4; k++) {
                    v[k].x *= inv; v[k].y *= inv; v[k].z *= inv; v[k].w *= inv;
                    sx4[r * RP4 + sub * 4 + k] = v[k];
                }
            }
        }
        if (threadIdx.x < TROWS) {
            int gr = gr0 + threadIdx.x;
            int bi = -1;
            if (gr >= 0 && gr < S) {
                const float* q = qmask + ((size_t)gr * B + b) * NSPK;
                float best = q[0]; bi = 0;
                for (int k = 1; k < NSPK; k++) {
                    float v = q[k];
                    if (v > best) { best = v; bi = k; }  // JAX first-max
                }
            }
            sspk[threadIdx.x] = bi;
        }
    }
    __syncthreads();

    // Phase B: warp w owns row i; lane jj owns neighbor j
    int w = threadIdx.x >> 5;
    int lane = threadIdx.x & 31;
    int i = i0 + w;
    if (i >= S) return;
    int li = WIN + w;
    bool valid_i = (i < len);
    int spk_i = sspk[li];

    int j = i - WIN + lane;
    int lj = w + lane;
    if (lj >= TROWS) lj = TROWS - 1;
    bool valid_j = (lane < WW) && valid_i && (j >= 0) && (j < len);
    bool same = valid_j && (sspk[lj] == spk_i);

    int cnt = __popc(__ballot_sync(0xffffffffu, same));

    float dot = 0.f;
    const float4* xi4 = sx4 + li * RP4;
    const float4* xj4 = sx4 + lj * RP4;
#pragma unroll
    for (int k = 0; k < DD/4; k++) {
        float4 a4 = xi4[k];            // broadcast
        float4 b4 = xj4[k];            // conflict-free strided
        dot += a4.x * b4.x + a4.y * b4.y + a4.z * b4.z + a4.w * b4.w;
    }

    float a = 0.f;
    if (valid_j) {
        float c = fminf(fmaxf(dot, -1.f), 1.f);
        a = angular_weight(c) * ((cnt > 1 && same) ? 2.f : 1.f);
    }

    float deg = a;
#pragma unroll
    for (int off = 16; off; off >>= 1)
        deg += __shfl_xor_sync(0xffffffffu, deg, off);

    if (lane < WW) g_band[(size_t)(base + i) * WW + lane] = a;
    if (lane == 0)
        g_dinv[base + i] = (deg > 0.f) ? rsqrtf(deg) : 1.f;
}

// ---------------- zero_rows: block-per-row zero writer, skips band chunks ----------------
__global__ __launch_bounds__(256)
void zero_rows_kernel(float* __restrict__ out, int B, int S) {
    int row = blockIdx.x;              // b*S + i
    int i = row % S;
    float* orow = out + (size_t)row * S;

    int jstart = max(i - WIN, 0);
    int jend   = min(i + WIN, S - 1);
    int clo = jstart >> 3;             // chunks [clo, chi] handled by patch
    int chi = jend >> 3;

    const float4 z = make_float4(0.f, 0.f, 0.f, 0.f);
    int nch = S >> 3;
    for (int c = threadIdx.x; c < nch; c += blockDim.x) {
        if (c < clo || c > chi)
            stg256_cs(orow + (c << 3), z, z);
    }
}

// ---------------- patch: write the skipped chunks with band values ----------------
__global__ __launch_bounds__(256)
void patch_kernel(float* __restrict__ out, int B, int S) {
    int warp = (blockIdx.x * blockDim.x + threadIdx.x) >> 5;
    int lane = threadIdx.x & 31;
    if (warp >= B * S) return;
    int b = warp / S, i = warp % S;

    int jstart = max(i - WIN, 0);
    int jend   = min(i + WIN, S - 1);
    int clo = jstart >> 3;
    int chi = jend >> 3;
    int p0 = clo << 3;                 // first float covered
    int p1 = (chi << 3) + 7;           // last float covered (< S since S%8==0)

    float di = g_dinv[warp];
    const float* bp = g_band + (size_t)warp * WW;
    float* orow = out + (size_t)warp * S;

#pragma unroll
    for (int pass = 0; pass < 2; pass++) {
        int j = p0 + pass * 32 + lane;
        if (j <= p1) {
            int d = j - (i - WIN);
            float v = (d >= 0 && d < WW)
                      ? bp[d] * di * g_dinv[b * S + j] : 0.f;
            orow[j] = v;
        }
    }
}

extern "C" void kernel_launch(void* const* d_in, const int* in_sizes, int n_in,
                              void* d_out, int out_size) {
    const float* x       = (const float*)d_in[0];
    const float* qmask   = (const float*)d_in[1];
    const int*   dia_len = (const int*)d_in[2];
    float* out = (float*)d_out;

    int B = in_sizes[2];
    int S = in_sizes[0] / (B * DD);
    int NSPK = in_sizes[1] / (B * S);
    int n = B * S;

    static cudaStream_t s2 = nullptr;
    static cudaEvent_t e_fork = nullptr, e_join = nullptr;
    if (!s2) {
        cudaStreamCreateWithFlags(&s2, cudaStreamNonBlocking);
        cudaEventCreateWithFlags(&e_fork, cudaEventDisableTiming);
        cudaEventCreateWithFlags(&e_join, cudaEventDisableTiming);
    }

    // fork: bandprep on side stream, concurrent with zero fill
    cudaEventRecord(e_fork, 0);
    cudaStreamWaitEvent(s2, e_fork, 0);

    dim3 bgrid((S + RPB - 1) / RPB, B);
    bandprep_kernel<<<bgrid, 256, 0, s2>>>(x, qmask, dia_len, B, S, NSPK);
    cudaEventRecord(e_join, s2);

    zero_rows_kernel<<<n, 256>>>(out, B, S);

    // join: patch band chunks
    cudaStreamWaitEvent(0, e_join, 0);
    patch_kernel<<<(n * 32 + 255) / 256, 256>>>(out, B, S);
}

// round 11
// speedup vs baseline: 1.3910x; 1.1795x over previous
#include <cuda_runtime.h>
#include <math.h>

#define DD 128
#define WIN 15
#define WW (2*WIN+1)          // 31
#define MAXB 4
#define MAXS 4096
#define TILE 16               // central rows per dotprep block
#define TR2 (TILE + WIN)      // 31 smem rows (forward halo only)
#define RPAD 132
#define RP4  (RPAD/4)         // 33

__device__ float g_dotf[(size_t)MAXB*MAXS*WIN];   // forward dots [row][15]
__device__ int   g_spk[MAXB*MAXS];
__device__ float g_band[(size_t)MAXB*MAXS*WW];
__device__ float g_dinv[MAXB*MAXS];

__device__ __forceinline__ void stg256_cs(float* p, const float4& a, const float4& b) {
    asm volatile("st.global.cs.v8.f32 [%0], {%1,%2,%3,%4,%5,%6,%7,%8};"
                 :: "l"(p),
                    "f"(a.x), "f"(a.y), "f"(a.z), "f"(a.w),
                    "f"(b.x), "f"(b.y), "f"(b.z), "f"(b.w)
                 : "memory");
}

// fast acos: Abramowitz-Stegun 4.4.45, |err| <= 6.7e-5 rad
__device__ __forceinline__ float angular_weight(float c) {
    float ax = fabsf(c);
    float s = sqrtf(fmaxf(1.f - ax, 0.f));
    float p = s * (1.5707288f + ax * (-0.2121144f + ax * (0.0742610f - ax * 0.0187293f)));
    float ac = (c >= 0.f) ? p : (3.14159265358979f - p);
    return 1.f - ac * 0.31830988618379067f;   // 1 - acos/pi
}

// ---------------- dotprep: normalize tile, forward dots only, speakers ----------------
__global__ __launch_bounds__(256)
void dotprep_kernel(const float* __restrict__ x,
                    const float* __restrict__ qmask,
                    int B, int S, int NSPK) {
    __shared__ float sx[TR2 * RPAD];

    int b  = blockIdx.y;
    int i0 = blockIdx.x * TILE;
    int base = b * S;

    float4* sx4 = (float4*)sx;
    const float4* x4g = (const float4*)(x + (size_t)base * DD);

    // Phase A: load rows [i0, i0+31), normalize into smem. Shfl is warp-converged.
    {
        int sub = threadIdx.x & 7;         // 8 threads/row, rows 0..31 in one pass
        int r = threadIdx.x >> 3;
        int gr = i0 + r;
        bool inb = (r < TR2) && (gr < S);
        float4 v[4];
        float ss = 0.f;
        if (inb) {
#pragma unroll
            for (int k = 0; k < 4; k++) {
                v[k] = x4g[(size_t)gr * (DD/4) + sub * 4 + k];
                ss += v[k].x * v[k].x + v[k].y * v[k].y
                    + v[k].z * v[k].z + v[k].w * v[k].w;
            }
        } else {
#pragma unroll
            for (int k = 0; k < 4; k++) v[k] = make_float4(0.f, 0.f, 0.f, 0.f);
        }
#pragma unroll
        for (int off = 4; off; off >>= 1)
            ss += __shfl_xor_sync(0xffffffffu, ss, off);
        float inv = 1.f / fmaxf(sqrtf(ss), 1e-8f);
        if (r < TR2) {
#pragma unroll
            for (int k = 0; k < 4; k++) {
                v[k].x *= inv; v[k].y *= inv; v[k].z *= inv; v[k].w *= inv;
                sx4[r * RP4 + sub * 4 + k] = v[k];
            }
        }
        // speakers for owned rows [i0, i0+16)
        if (threadIdx.x < TILE) {
            int g2 = i0 + threadIdx.x;
            if (g2 < S) {
                const float* q = qmask + ((size_t)g2 * B + b) * NSPK;
                float best = q[0]; int bi = 0;
                for (int k = 1; k < NSPK; k++) {
                    float vq = q[k];
                    if (vq > best) { best = vq; bi = k; }  // JAX first-max
                }
                g_spk[base + g2] = bi;
            }
        }
    }
    __syncthreads();

    // Phase B: warp w owns rows i0+2w, i0+2w+1; lane = (half, offset o in 0..14)
    int w = threadIdx.x >> 5;
    int lane = threadIdx.x & 31;
    int half = lane >> 4;
    int o = lane & 15;
    int rl = 2 * w + half;                 // tile row 0..15
    int i = i0 + rl;
    bool active = (o < 15) && (i < S);
    int jl = rl + 1 + o;                   // <= 30 when active
    int jlc = active ? jl : rl;            // safe smem row for inactive lanes

    float dot = 0.f;
    const float4* xi4 = sx4 + rl * RP4;
    const float4* xj4 = sx4 + jlc * RP4;
#pragma unroll
    for (int k = 0; k < DD/4; k++) {
        float4 a4 = xi4[k];
        float4 b4 = xj4[k];
        dot += a4.x * b4.x + a4.y * b4.y + a4.z * b4.z + a4.w * b4.w;
    }
    if (active)
        g_dotf[(size_t)(base + i) * WIN + o] = dot;
}

// ---------------- assemble: gather band dots, weights, cnt, deg ----------------
__global__ __launch_bounds__(256)
void assemble_kernel(const int* __restrict__ dia_len, int B, int S) {
    int gw = (blockIdx.x * blockDim.x + threadIdx.x) >> 5;
    int lane = threadIdx.x & 31;
    if (gw >= B * S) return;
    int b = gw / S, i = gw % S;
    int base = b * S;
    int len = dia_len[b];
    bool valid_i = (i < len);

    int j = i - WIN + lane;
    bool inr = (lane < WW) && (j >= 0) && (j < S);

    float dot = 0.f;
    if (lane < WIN) {
        if (j >= 0) dot = g_dotf[(size_t)(base + j) * WIN + (14 - lane)];
    } else if (lane == WIN) {
        dot = 1.f;                          // diagonal
    } else if (lane < WW) {
        if (j < S) dot = g_dotf[(size_t)(base + i) * WIN + (lane - 16)];
    }

    int spk_i = g_spk[base + i];
    int spk_j = inr ? g_spk[base + j] : -1;
    bool valid_j = valid_i && inr && (j < len);
    bool same = valid_j && (spk_j == spk_i);
    int cnt = __popc(__ballot_sync(0xffffffffu, same));

    float a = 0.f;
    if (valid_j) {
        float c = fminf(fmaxf(dot, -1.f), 1.f);
        a = angular_weight(c) * ((cnt > 1 && same) ? 2.f : 1.f);
    }

    float deg = a;
#pragma unroll
    for (int off = 16; off; off >>= 1)
        deg += __shfl_xor_sync(0xffffffffu, deg, off);

    if (lane < WW) g_band[(size_t)gw * WW + lane] = a;
    if (lane == 0)
        g_dinv[gw] = (deg > 0.f) ? rsqrtf(deg) : 1.f;
}

// ---------------- zero_rows: block-per-row zero writer, skips band chunks ----------------
__global__ __launch_bounds__(256)
void zero_rows_kernel(float* __restrict__ out, int B, int S) {
    int row = blockIdx.x;
    int i = row % S;
    float* orow = out + (size_t)row * S;

    int jstart = max(i - WIN, 0);
    int jend   = min(i + WIN, S - 1);
    int clo = jstart >> 3;
    int chi = jend >> 3;

    const float4 z = make_float4(0.f, 0.f, 0.f, 0.f);
    int nch = S >> 3;
    for (int c = threadIdx.x; c < nch; c += blockDim.x) {
        if (c < clo || c > chi)
            stg256_cs(orow + (c << 3), z, z);
    }
}

// ---------------- patch: write the skipped chunks with band values ----------------
__global__ __launch_bounds__(256)
void patch_kernel(float* __restrict__ out, int B, int S) {
    int warp = (blockIdx.x * blockDim.x + threadIdx.x) >> 5;
    int lane = threadIdx.x & 31;
    if (warp >= B * S) return;
    int b = warp / S, i = warp % S;

    int jstart = max(i - WIN, 0);
    int jend   = min(i + WIN, S - 1);
    int clo = jstart >> 3;
    int chi = jend >> 3;
    int p0 = clo << 3;
    int p1 = (chi << 3) + 7;

    float di = g_dinv[warp];
    const float* bp = g_band + (size_t)warp * WW;
    float* orow = out + (size_t)warp * S;

#pragma unroll
    for (int pass = 0; pass < 2; pass++) {
        int j = p0 + pass * 32 + lane;
        if (j <= p1) {
            int d = j - (i - WIN);
            float v = (d >= 0 && d < WW)
                      ? bp[d] * di * g_dinv[b * S + j] : 0.f;
            orow[j] = v;
        }
    }
}

extern "C" void kernel_launch(void* const* d_in, const int* in_sizes, int n_in,
                              void* d_out, int out_size) {
    const float* x       = (const float*)d_in[0];
    const float* qmask   = (const float*)d_in[1];
    const int*   dia_len = (const int*)d_in[2];
    float* out = (float*)d_out;

    int B = in_sizes[2];
    int S = in_sizes[0] / (B * DD);
    int NSPK = in_sizes[1] / (B * S);
    int n = B * S;

    static cudaStream_t s2 = nullptr;
    static cudaEvent_t e_fork = nullptr, e_join = nullptr;
    if (!s2) {
        cudaStreamCreateWithFlags(&s2, cudaStreamNonBlocking);
        cudaEventCreateWithFlags(&e_fork, cudaEventDisableTiming);
        cudaEventCreateWithFlags(&e_join, cudaEventDisableTiming);
    }

    // fork: band pipeline on side stream, concurrent with zero fill
    cudaEventRecord(e_fork, 0);
    cudaStreamWaitEvent(s2, e_fork, 0);

    dim3 dgrid((S + TILE - 1) / TILE, B);
    dotprep_kernel<<<dgrid, 256, 0, s2>>>(x, qmask, B, S, NSPK);
    assemble_kernel<<<(n * 32 + 255) / 256, 256, 0, s2>>>(dia_len, B, S);
    cudaEventRecord(e_join, s2);

    zero_rows_kernel<<<n, 256>>>(out, B, S);

    // join: patch band chunks
    cudaStreamWaitEvent(0, e_join, 0);
    patch_kernel<<<(n * 32 + 255) / 256, 256>>>(out, B, S);
}

// round 12
// speedup vs baseline: 1.4191x; 1.0202x over previous
#include <cuda_runtime.h>
#include <math.h>

#define DD 128
#define WIN 15
#define WW (2*WIN+1)          // 31
#define MAXB 4
#define MAXS 4096
#define TILE 16               // central rows per dotprep block
#define TR2 (TILE + WIN)      // 31 smem rows (forward halo only)
#define RPAD 132
#define RP4  (RPAD/4)         // 33

__device__ float g_dotf[(size_t)MAXB*MAXS*WIN];   // forward dots [row][15]
__device__ int   g_spk[MAXB*MAXS];
__device__ float g_band[(size_t)MAXB*MAXS*WW];
__device__ float g_dinv[MAXB*MAXS];

__device__ __forceinline__ void stg256_cs(float* p, const float4& a, const float4& b) {
    asm volatile("st.global.cs.v8.f32 [%0], {%1,%2,%3,%4,%5,%6,%7,%8};"
                 :: "l"(p),
                    "f"(a.x), "f"(a.y), "f"(a.z), "f"(a.w),
                    "f"(b.x), "f"(b.y), "f"(b.z), "f"(b.w)
                 : "memory");
}

// fast acos: Abramowitz-Stegun 4.4.45, |err| <= 6.7e-5 rad
__device__ __forceinline__ float angular_weight(float c) {
    float ax = fabsf(c);
    float s = sqrtf(fmaxf(1.f - ax, 0.f));
    float p = s * (1.5707288f + ax * (-0.2121144f + ax * (0.0742610f - ax * 0.0187293f)));
    float ac = (c >= 0.f) ? p : (3.14159265358979f - p);
    return 1.f - ac * 0.31830988618379067f;   // 1 - acos/pi
}

// ---------------- dotprep: normalize tile, forward dots only, speakers ----------------
__global__ __launch_bounds__(256)
void dotprep_kernel(const float* __restrict__ x,
                    const float* __restrict__ qmask,
                    int B, int S, int NSPK) {
    __shared__ float sx[TR2 * RPAD];

    int b  = blockIdx.y;
    int i0 = blockIdx.x * TILE;
    int base = b * S;

    float4* sx4 = (float4*)sx;
    const float4* x4g = (const float4*)(x + (size_t)base * DD);

    // Phase A: load rows [i0, i0+31), normalize into smem. Shfl warp-converged.
    {
        int sub = threadIdx.x & 7;
        int r = threadIdx.x >> 3;
        int gr = i0 + r;
        bool inb = (r < TR2) && (gr < S);
        float4 v[4];
        float ss = 0.f;
        if (inb) {
#pragma unroll
            for (int k = 0; k < 4; k++) {
                v[k] = x4g[(size_t)gr * (DD/4) + sub * 4 + k];
                ss += v[k].x * v[k].x + v[k].y * v[k].y
                    + v[k].z * v[k].z + v[k].w * v[k].w;
            }
        } else {
#pragma unroll
            for (int k = 0; k < 4; k++) v[k] = make_float4(0.f, 0.f, 0.f, 0.f);
        }
#pragma unroll
        for (int off = 4; off; off >>= 1)
            ss += __shfl_xor_sync(0xffffffffu, ss, off);
        float inv = 1.f / fmaxf(sqrtf(ss), 1e-8f);
        if (r < TR2) {
#pragma unroll
            for (int k = 0; k < 4; k++) {
                v[k].x *= inv; v[k].y *= inv; v[k].z *= inv; v[k].w *= inv;
                sx4[r * RP4 + sub * 4 + k] = v[k];
            }
        }
        if (threadIdx.x < TILE) {
            int g2 = i0 + threadIdx.x;
            if (g2 < S) {
                const float* q = qmask + ((size_t)g2 * B + b) * NSPK;
                float best = q[0]; int bi = 0;
                for (int k = 1; k < NSPK; k++) {
                    float vq = q[k];
                    if (vq > best) { best = vq; bi = k; }  // JAX first-max
                }
                g_spk[base + g2] = bi;
            }
        }
    }
    __syncthreads();

    // Phase B: warp w owns rows i0+2w(+1); lane = (half, offset o in 0..14)
    int w = threadIdx.x >> 5;
    int lane = threadIdx.x & 31;
    int half = lane >> 4;
    int o = lane & 15;
    int rl = 2 * w + half;
    int i = i0 + rl;
    bool active = (o < 15) && (i < S);
    int jl = rl + 1 + o;
    int jlc = active ? jl : rl;

    float dot = 0.f;
    const float4* xi4 = sx4 + rl * RP4;
    const float4* xj4 = sx4 + jlc * RP4;
#pragma unroll
    for (int k = 0; k < DD/4; k++) {
        float4 a4 = xi4[k];
        float4 b4 = xj4[k];
        dot += a4.x * b4.x + a4.y * b4.y + a4.z * b4.z + a4.w * b4.w;
    }
    if (active)
        g_dotf[(size_t)(base + i) * WIN + o] = dot;
}

// ---------------- assemble: gather band dots, weights, cnt, deg ----------------
__global__ __launch_bounds__(256)
void assemble_kernel(const int* __restrict__ dia_len, int B, int S) {
    int gw = (blockIdx.x * blockDim.x + threadIdx.x) >> 5;
    int lane = threadIdx.x & 31;
    if (gw >= B * S) return;
    int b = gw / S, i = gw % S;
    int base = b * S;
    int len = dia_len[b];
    bool valid_i = (i < len);

    int j = i - WIN + lane;
    bool inr = (lane < WW) && (j >= 0) && (j < S);

    float dot = 0.f;
    if (lane < WIN) {
        if (j >= 0) dot = g_dotf[(size_t)(base + j) * WIN + (14 - lane)];
    } else if (lane == WIN) {
        dot = 1.f;                          // diagonal
    } else if (lane < WW) {
        if (j < S) dot = g_dotf[(size_t)(base + i) * WIN + (lane - 16)];
    }

    int spk_i = g_spk[base + i];
    int spk_j = inr ? g_spk[base + j] : -1;
    bool valid_j = valid_i && inr && (j < len);
    bool same = valid_j && (spk_j == spk_i);
    int cnt = __popc(__ballot_sync(0xffffffffu, same));

    float a = 0.f;
    if (valid_j) {
        float c = fminf(fmaxf(dot, -1.f), 1.f);
        a = angular_weight(c) * ((cnt > 1 && same) ? 2.f : 1.f);
    }

    float deg = a;
#pragma unroll
    for (int off = 16; off; off >>= 1)
        deg += __shfl_xor_sync(0xffffffffu, deg, off);

    if (lane < WW) g_band[(size_t)gw * WW + lane] = a;
    if (lane == 0)
        g_dinv[gw] = (deg > 0.f) ? rsqrtf(deg) : 1.f;
}

// ---------------- zero_rows: block-per-row zero writer, skips band chunks ----------------
__global__ __launch_bounds__(256)
void zero_rows_kernel(float* __restrict__ out, int B, int S) {
    int row = blockIdx.x;
    int i = row % S;
    float* orow = out + (size_t)row * S;

    int jstart = max(i - WIN, 0);
    int jend   = min(i + WIN, S - 1);
    int clo = jstart >> 3;
    int chi = jend >> 3;

    const float4 z = make_float4(0.f, 0.f, 0.f, 0.f);
    int nch = S >> 3;
    for (int c = threadIdx.x; c < nch; c += blockDim.x) {
        if (c < clo || c > chi)
            stg256_cs(orow + (c << 3), z, z);
    }
}

// ---------------- patch: write the skipped chunks (disjoint sectors vs zero) ----------------
__global__ __launch_bounds__(256)
void patch_kernel(float* __restrict__ out, int B, int S) {
    int warp = (blockIdx.x * blockDim.x + threadIdx.x) >> 5;
    int lane = threadIdx.x & 31;
    if (warp >= B * S) return;
    int b = warp / S, i = warp % S;

    int jstart = max(i - WIN, 0);
    int jend   = min(i + WIN, S - 1);
    int clo = jstart >> 3;
    int chi = jend >> 3;
    int p0 = clo << 3;
    int p1 = (chi << 3) + 7;

    float di = g_dinv[warp];
    const float* bp = g_band + (size_t)warp * WW;
    float* orow = out + (size_t)warp * S;

#pragma unroll
    for (int pass = 0; pass < 2; pass++) {
        int j = p0 + pass * 32 + lane;
        if (j <= p1) {
            int d = j - (i - WIN);
            float v = (d >= 0 && d < WW)
                      ? bp[d] * di * g_dinv[b * S + j] : 0.f;
            orow[j] = v;
        }
    }
}

extern "C" void kernel_launch(void* const* d_in, const int* in_sizes, int n_in,
                              void* d_out, int out_size) {
    const float* x       = (const float*)d_in[0];
    const float* qmask   = (const float*)d_in[1];
    const int*   dia_len = (const int*)d_in[2];
    float* out = (float*)d_out;

    int B = in_sizes[2];
    int S = in_sizes[0] / (B * DD);
    int NSPK = in_sizes[1] / (B * S);
    int n = B * S;

    static cudaStream_t s2 = nullptr;
    static cudaEvent_t e_fork = nullptr, e_join = nullptr;
    if (!s2) {
        cudaStreamCreateWithFlags(&s2, cudaStreamNonBlocking);
        cudaEventCreateWithFlags(&e_fork, cudaEventDisableTiming);
        cudaEventCreateWithFlags(&e_join, cudaEventDisableTiming);
    }

    // fork: entire band pipeline INCLUDING patch on side stream.
    // patch writes only the chunks zero_rows skips (disjoint 32B sectors),
    // so it needs no ordering against zero_rows.
    cudaEventRecord(e_fork, 0);
    cudaStreamWaitEvent(s2, e_fork, 0);

    dim3 dgrid((S + TILE - 1) / TILE, B);
    dotprep_kernel<<<dgrid, 256, 0, s2>>>(x, qmask, B, S, NSPK);
    assemble_kernel<<<(n * 32 + 255) / 256, 256, 0, s2>>>(dia_len, B, S);
    patch_kernel<<<(n * 32 + 255) / 256, 256, 0, s2>>>(out, B, S);
    cudaEventRecord(e_join, s2);

    // main stream: the big zero fill, concurrent with the side pipeline
    zero_rows_kernel<<<n, 256>>>(out, B, S);

    // join: main stream completes only after side pipeline is done
    cudaStreamWaitEvent(0, e_join, 0);
}

// round 13
// speedup vs baseline: 1.4208x; 1.0012x over previous
#include <cuda_runtime.h>
#include <math.h>

#define DD 128
#define WIN 15
#define WW (2*WIN+1)          // 31
#define MAXB 4
#define MAXS 4096
#define TILE 16               // central rows per dotprep block
#define TR2 (TILE + WIN)      // 31 smem rows (forward halo only)
#define RPAD 132
#define RP4  (RPAD/4)         // 33

__device__ float g_dotf[(size_t)MAXB*MAXS*WIN];   // forward dots [row][15]
__device__ int   g_spk[MAXB*MAXS];
__device__ float g_band[(size_t)MAXB*MAXS*WW];
__device__ float g_dinv[MAXB*MAXS];

__device__ __forceinline__ void stg256_cs(float* p, const float4& a, const float4& b) {
    asm volatile("st.global.cs.v8.f32 [%0], {%1,%2,%3,%4,%5,%6,%7,%8};"
                 :: "l"(p),
                    "f"(a.x), "f"(a.y), "f"(a.z), "f"(a.w),
                    "f"(b.x), "f"(b.y), "f"(b.z), "f"(b.w)
                 : "memory");
}

// fast acos: Abramowitz-Stegun 4.4.45, |err| <= 6.7e-5 rad
__device__ __forceinline__ float angular_weight(float c) {
    float ax = fabsf(c);
    float s = sqrtf(fmaxf(1.f - ax, 0.f));
    float p = s * (1.5707288f + ax * (-0.2121144f + ax * (0.0742610f - ax * 0.0187293f)));
    float ac = (c >= 0.f) ? p : (3.14159265358979f - p);
    return 1.f - ac * 0.31830988618379067f;   // 1 - acos/pi
}

// ---------------- dotprep: normalize tile, forward dots only, speakers ----------------
__global__ __launch_bounds__(256)
void dotprep_kernel(const float* __restrict__ x,
                    const float* __restrict__ qmask,
                    int B, int S, int NSPK) {
    __shared__ float sx[TR2 * RPAD];

    int b  = blockIdx.y;
    int i0 = blockIdx.x * TILE;
    int base = b * S;

    float4* sx4 = (float4*)sx;
    const float4* x4g = (const float4*)(x + (size_t)base * DD);

    // Phase A: load rows [i0, i0+31), normalize into smem. Shfl warp-converged.
    {
        int sub = threadIdx.x & 7;
        int r = threadIdx.x >> 3;
        int gr = i0 + r;
        bool inb = (r < TR2) && (gr < S);
        float4 v[4];
        float ss = 0.f;
        if (inb) {
#pragma unroll
            for (int k = 0; k < 4; k++) {
                v[k] = x4g[(size_t)gr * (DD/4) + sub * 4 + k];
                ss += v[k].x * v[k].x + v[k].y * v[k].y
                    + v[k].z * v[k].z + v[k].w * v[k].w;
            }
        } else {
#pragma unroll
            for (int k = 0; k < 4; k++) v[k] = make_float4(0.f, 0.f, 0.f, 0.f);
        }
#pragma unroll
        for (int off = 4; off; off >>= 1)
            ss += __shfl_xor_sync(0xffffffffu, ss, off);
        float inv = 1.f / fmaxf(sqrtf(ss), 1e-8f);
        if (r < TR2) {
#pragma unroll
            for (int k = 0; k < 4; k++) {
                v[k].x *= inv; v[k].y *= inv; v[k].z *= inv; v[k].w *= inv;
                sx4[r * RP4 + sub * 4 + k] = v[k];
            }
        }
        if (threadIdx.x < TILE) {
            int g2 = i0 + threadIdx.x;
            if (g2 < S) {
                const float* q = qmask + ((size_t)g2 * B + b) * NSPK;
                float best = q[0]; int bi = 0;
                for (int k = 1; k < NSPK; k++) {
                    float vq = q[k];
                    if (vq > best) { best = vq; bi = k; }  // JAX first-max
                }
                g_spk[base + g2] = bi;
            }
        }
    }
    __syncthreads();

    // Phase B: warp w owns rows i0+2w(+1); lane = (half, offset o in 0..14)
    int w = threadIdx.x >> 5;
    int lane = threadIdx.x & 31;
    int half = lane >> 4;
    int o = lane & 15;
    int rl = 2 * w + half;
    int i = i0 + rl;
    bool active = (o < 15) && (i < S);
    int jl = rl + 1 + o;
    int jlc = active ? jl : rl;

    float dot = 0.f;
    const float4* xi4 = sx4 + rl * RP4;
    const float4* xj4 = sx4 + jlc * RP4;
#pragma unroll
    for (int k = 0; k < DD/4; k++) {
        float4 a4 = xi4[k];
        float4 b4 = xj4[k];
        dot += a4.x * b4.x + a4.y * b4.y + a4.z * b4.z + a4.w * b4.w;
    }
    if (active)
        g_dotf[(size_t)(base + i) * WIN + o] = dot;
}

// ---------------- assemble: gather band dots, weights, cnt, deg ----------------
__global__ __launch_bounds__(256)
void assemble_kernel(const int* __restrict__ dia_len, int B, int S) {
    int gw = (blockIdx.x * blockDim.x + threadIdx.x) >> 5;
    int lane = threadIdx.x & 31;
    if (gw >= B * S) return;
    int b = gw / S, i = gw % S;
    int base = b * S;
    int len = dia_len[b];
    bool valid_i = (i < len);

    int j = i - WIN + lane;
    bool inr = (lane < WW) && (j >= 0) && (j < S);

    float dot = 0.f;
    if (lane < WIN) {
        if (j >= 0) dot = g_dotf[(size_t)(base + j) * WIN + (14 - lane)];
    } else if (lane == WIN) {
        dot = 1.f;                          // diagonal
    } else if (lane < WW) {
        if (j < S) dot = g_dotf[(size_t)(base + i) * WIN + (lane - 16)];
    }

    int spk_i = g_spk[base + i];
    int spk_j = inr ? g_spk[base + j] : -1;
    bool valid_j = valid_i && inr && (j < len);
    bool same = valid_j && (spk_j == spk_i);
    int cnt = __popc(__ballot_sync(0xffffffffu, same));

    float a = 0.f;
    if (valid_j) {
        float c = fminf(fmaxf(dot, -1.f), 1.f);
        a = angular_weight(c) * ((cnt > 1 && same) ? 2.f : 1.f);
    }

    float deg = a;
#pragma unroll
    for (int off = 16; off; off >>= 1)
        deg += __shfl_xor_sync(0xffffffffu, deg, off);

    if (lane < WW) g_band[(size_t)gw * WW + lane] = a;
    if (lane == 0)
        g_dinv[gw] = (deg > 0.f) ? rsqrtf(deg) : 1.f;
}

// ---------------- zero_rows: block-per-row zero writer, skips band chunks ----------------
__global__ __launch_bounds__(256)
void zero_rows_kernel(float* __restrict__ out, int B, int S) {
    int row = blockIdx.x;
    int i = row % S;
    float* orow = out + (size_t)row * S;

    int jstart = max(i - WIN, 0);
    int jend   = min(i + WIN, S - 1);
    int clo = jstart >> 3;
    int chi = jend >> 3;

    const float4 z = make_float4(0.f, 0.f, 0.f, 0.f);
    int nch = S >> 3;
    for (int c = threadIdx.x; c < nch; c += blockDim.x) {
        if (c < clo || c > chi)
            stg256_cs(orow + (c << 3), z, z);
    }
}

// ---------------- patch: write the skipped chunks (disjoint sectors vs zero) ----------------
__global__ __launch_bounds__(256)
void patch_kernel(float* __restrict__ out, int B, int S) {
    int warp = (blockIdx.x * blockDim.x + threadIdx.x) >> 5;
    int lane = threadIdx.x & 31;
    if (warp >= B * S) return;
    int b = warp / S, i = warp % S;

    int jstart = max(i - WIN, 0);
    int jend   = min(i + WIN, S - 1);
    int clo = jstart >> 3;
    int chi = jend >> 3;
    int p0 = clo << 3;
    int p1 = (chi << 3) + 7;

    float di = g_dinv[warp];
    const float* bp = g_band + (size_t)warp * WW;
    float* orow = out + (size_t)warp * S;

#pragma unroll
    for (int pass = 0; pass < 2; pass++) {
        int j = p0 + pass * 32 + lane;
        if (j <= p1) {
            int d = j - (i - WIN);
            float v = (d >= 0 && d < WW)
                      ? bp[d] * di * g_dinv[b * S + j] : 0.f;
            orow[j] = v;
        }
    }
}

extern "C" void kernel_launch(void* const* d_in, const int* in_sizes, int n_in,
                              void* d_out, int out_size) {
    const float* x       = (const float*)d_in[0];
    const float* qmask   = (const float*)d_in[1];
    const int*   dia_len = (const int*)d_in[2];
    float* out = (float*)d_out;

    int B = in_sizes[2];
    int S = in_sizes[0] / (B * DD);
    int NSPK = in_sizes[1] / (B * S);
    int n = B * S;

    // side stream at GREATEST priority so its blocks preempt the zero flood
    static cudaStream_t s2 = nullptr;
    static cudaEvent_t e_fork = nullptr, e_join = nullptr;
    if (!s2) {
        int lo, hi;
        cudaDeviceGetStreamPriorityRange(&lo, &hi);   // hi = greatest priority
        cudaStreamCreateWithPriority(&s2, cudaStreamNonBlocking, hi);
        cudaEventCreateWithFlags(&e_fork, cudaEventDisableTiming);
        cudaEventCreateWithFlags(&e_join, cudaEventDisableTiming);
    }

    // fork: band pipeline (incl. patch — disjoint 32B sectors vs zero) on
    // the high-priority side stream, concurrent with the zero fill.
    cudaEventRecord(e_fork, 0);
    cudaStreamWaitEvent(s2, e_fork, 0);

    dim3 dgrid((S + TILE - 1) / TILE, B);
    dotprep_kernel<<<dgrid, 256, 0, s2>>>(x, qmask, B, S, NSPK);
    assemble_kernel<<<(n * 32 + 255) / 256, 256, 0, s2>>>(dia_len, B, S);
    patch_kernel<<<(n * 32 + 255) / 256, 256, 0, s2>>>(out, B, S);
    cudaEventRecord(e_join, s2);

    // main stream: the big zero fill
    zero_rows_kernel<<<n, 256>>>(out, B, S);

    // join
    cudaStreamWaitEvent(0, e_join, 0);
}